// round 5
// baseline (speedup 1.0000x reference)
#include <cuda_runtime.h>
#include <cuda_bf16.h>
#include <cstdint>

#define LSEQ 128
#define DDIM 768
#define NBATCH 8
#define ROWS (NBATCH * LSEQ)   // 1024

// ---------------- scratch (__device__ globals; no allocation) ----------------
__device__ float g_hh[2][ROWS * DDIM];   // hi, hj (fp32)
__device__ float g_a[NBATCH * LSEQ * LSEQ];
__device__ float g_denom[ROWS];
__device__ float g_t[ROWS * DDIM];
__device__ float g_y[ROWS * DDIM];
__device__ float g_buf[2][ROWS * DDIM];
__device__ __align__(16) __nv_bfloat16 g_hj2[ROWS * DDIM];      // hj bf16
// w2 pre-shuffled into m16n8k16 B-fragment order: [nn 0..47][kk 0..47][lane 0..31] uint2
__device__ __align__(16) uint2 g_bfrag[48 * 48 * 32];

// ============================================================================
// PTX helpers (baseline features only)
// ============================================================================
__device__ __forceinline__ uint32_t smem_to_u32(const void* p) {
    uint32_t a;
    asm("{ .reg .u64 t; cvta.to.shared.u64 t, %1; cvt.u32.u64 %0, t; }" : "=r"(a) : "l"(p));
    return a;
}
__device__ __forceinline__ void ldsm_x4(uint32_t& r0, uint32_t& r1, uint32_t& r2,
                                        uint32_t& r3, uint32_t addr) {
    asm volatile("ldmatrix.sync.aligned.m8n8.x4.shared.b16 {%0,%1,%2,%3}, [%4];"
                 : "=r"(r0), "=r"(r1), "=r"(r2), "=r"(r3) : "r"(addr));
}
__device__ __forceinline__ void mma_bf16(float* c, const uint32_t* a, const uint32_t* b) {
    asm volatile("mma.sync.aligned.m16n8k16.row.col.f32.bf16.bf16.f32 "
                 "{%0,%1,%2,%3}, {%4,%5,%6,%7}, {%8,%9}, {%0,%1,%2,%3};"
                 : "+f"(c[0]), "+f"(c[1]), "+f"(c[2]), "+f"(c[3])
                 : "r"(a[0]), "r"(a[1]), "r"(a[2]), "r"(a[3]), "r"(b[0]), "r"(b[1]));
}

// ---------------- generic NN fp32 GEMM: C = A@B (+Cadd), row-major ----------
__global__ __launch_bounds__(256)
void gemm_nn64(const float* __restrict__ A, const float* __restrict__ B,
               float* __restrict__ C, const float* __restrict__ Cadd,
               int M, int N, int K, long sA, long sB, long sC)
{
    const int bz = blockIdx.z;
    A += (long)bz * sA;
    B += (long)bz * sB;
    const long coff = (long)bz * sC;

    const int bm = blockIdx.y * 64;
    const int bn = blockIdx.x * 64;

    __shared__ float As[32][64];
    __shared__ float Bs[32][64];

    const int tid = threadIdx.x;
    const int tx = tid & 15;
    const int ty = tid >> 4;

    float acc[4][4] = {};

    for (int kc = 0; kc < K; kc += 32) {
        #pragma unroll
        for (int it = 0; it < 2; it++) {
            int idx = tid * 4 + it * 1024;
            int m = idx >> 5;
            int k = idx & 31;
            float4 v = *(const float4*)(A + (long)(bm + m) * K + kc + k);
            As[k + 0][m] = v.x; As[k + 1][m] = v.y;
            As[k + 2][m] = v.z; As[k + 3][m] = v.w;
        }
        #pragma unroll
        for (int it = 0; it < 2; it++) {
            int idx = tid * 4 + it * 1024;
            int k = idx >> 6;
            int n = idx & 63;
            *(float4*)&Bs[k][n] = *(const float4*)(B + (long)(kc + k) * N + bn + n);
        }
        __syncthreads();

        #pragma unroll
        for (int k = 0; k < 32; k++) {
            float av[4], bv[4];
            *(float4*)av = *(const float4*)&As[k][ty * 4];
            *(float4*)bv = *(const float4*)&Bs[k][tx * 4];
            #pragma unroll
            for (int r = 0; r < 4; r++)
                #pragma unroll
                for (int c = 0; c < 4; c++)
                    acc[r][c] += av[r] * bv[c];
        }
        __syncthreads();
    }

    #pragma unroll
    for (int r = 0; r < 4; r++) {
        long off = coff + (long)(bm + ty * 4 + r) * N + bn + tx * 4;
        float4 v = *(float4*)acc[r];
        if (Cadd) {
            float4 w = *(const float4*)(Cadd + off);
            v.x += w.x; v.y += w.y; v.z += w.z; v.w += w.w;
        }
        *(float4*)(C + off) = v;
    }
}

// ---------------- prep: w2 -> B fragments, hj -> bf16 ------------------------
// m16n8k16 B fragment (row.col): lane l holds
//   b0 = { B[k0][n], B[k0+1][n] },  b1 = { B[k0+8][n], B[k0+9][n] }
// with n = nn*8 + l/4, k0 = kk*16 + 2*(l%4).   B[k][n] = w2[k*384 + n].
__global__ void prep_bfrag(const float* __restrict__ w2, uint2* __restrict__ bf)
{
    int idx = blockIdx.x * 256 + threadIdx.x;
    if (idx < 48 * 48 * 32) {
        int lane = idx & 31;
        int kk = (idx >> 5) % 48;
        int nn = idx / (48 * 32);
        int n  = nn * 8 + (lane >> 2);
        int k0 = kk * 16 + 2 * (lane & 3);
        __nv_bfloat162 b0 = __floats2bfloat162_rn(w2[k0 * 384 + n], w2[(k0 + 1) * 384 + n]);
        __nv_bfloat162 b1 = __floats2bfloat162_rn(w2[(k0 + 8) * 384 + n], w2[(k0 + 9) * 384 + n]);
        uint2 o;
        o.x = *(uint32_t*)&b0;
        o.y = *(uint32_t*)&b1;
        bf[idx] = o;
    }
}
__global__ void prep_hj2(const float4* __restrict__ hj, uint2* __restrict__ hj2)
{
    int idx = blockIdx.x * 256 + threadIdx.x;
    if (idx < ROWS * DDIM / 4) {
        float4 v = hj[idx];
        __nv_bfloat162 lo = __floats2bfloat162_rn(v.x, v.y);
        __nv_bfloat162 hi = __floats2bfloat162_rn(v.z, v.w);
        uint2 o; o.x = *(uint32_t*)&lo; o.y = *(uint32_t*)&hi;
        hj2[idx] = o;
    }
}

// ============================================================================
// Fused edge-MLP via mma.sync bf16. One CTA per (b, i).
// Persistent A tile (128 x 768 bf16) built ONCE in SMEM; B fragments LDG'd
// directly from pre-shuffled global (L2-resident); barrier-free mainloop.
// ============================================================================
#define APITCH 1552                       // 768*2 + 16 pad (ldsm conflict-free)
#define SM_A     0
#define SM_HIB   198656                   // 128*1552
#define SM_B2    201728
#define SM_W3    203264
#define SM_SCAL  204800
#define SM_RED   205312
#define SM_TOTAL 205376

__global__ __launch_bounds__(256)
void edge_mma_kernel(const float* __restrict__ hi, const __nv_bfloat16* __restrict__ hj2,
                     const float* __restrict__ adj, const float* __restrict__ b1,
                     const uint2* __restrict__ bfrag, const float* __restrict__ b2,
                     const float* __restrict__ w3, const float* __restrict__ b3p,
                     float* __restrict__ a_out, float* __restrict__ denom_out)
{
    extern __shared__ char smem[];
    const uint32_t sbase = smem_to_u32(smem);
    const int tid  = threadIdx.x;
    const int lane = tid & 31;
    const int wid  = tid >> 5;
    const int warpM = wid >> 2;          // 0..1  (64 rows each)
    const int warpN = wid & 3;           // 0..3  (32 cols of the 128-col nc chunk)
    const int bi = blockIdx.x;
    const int b  = bi >> 7;
    const int i  = bi & 127;

    float* hib  = (float*)(smem + SM_HIB);
    float* b2s  = (float*)(smem + SM_B2);
    float* w3s  = (float*)(smem + SM_W3);
    float* scal = (float*)(smem + SM_SCAL);
    float* red  = (float*)(smem + SM_RED);

    for (int k = tid; k < DDIM; k += 256) hib[k] = hi[(long)bi * DDIM + k] + b1[k];
    for (int k = tid; k < 384; k += 256) { b2s[k] = b2[k]; w3s[k] = w3[k]; }
    if (tid < 128) scal[tid] = 0.f;
    __syncthreads();

    // ---------------- build persistent A tile (once) ----------------
    {
        const int aj = tid >> 1;         // row j
        const int ah = tid & 1;          // k-half (32 of 64 per chunk)
        const __nv_bfloat16* hjrow = hj2 + ((long)b * LSEQ + aj) * DDIM;
        char* arow = smem + SM_A + aj * APITCH;
        #pragma unroll
        for (int kc = 0; kc < 12; kc++) {
            const int k0 = kc * 64 + ah * 32;
            const uint4* src = (const uint4*)(hjrow + k0);
            const float* hb  = hib + k0;
            #pragma unroll
            for (int s = 0; s < 4; s++) {
                uint4 v = src[s];
                __nv_bfloat162* p = (__nv_bfloat162*)&v;
                uint4 o;
                uint32_t* po = (uint32_t*)&o;
                #pragma unroll
                for (int h = 0; h < 4; h++) {
                    float2 f = __bfloat1622float2(p[h]);
                    __nv_bfloat162 r = __floats2bfloat162_rn(
                        fmaxf(f.x + hb[s * 8 + h * 2], 0.f),
                        fmaxf(f.y + hb[s * 8 + h * 2 + 1], 0.f));
                    po[h] = *(uint32_t*)&r;
                }
                *(uint4*)(arow + (k0 + s * 8) * 2) = o;
            }
        }
    }
    __syncthreads();

    // ---------------- mainloop: 3 nc passes, barrier-free ----------------
    const uint32_t a_lane_base = sbase + SM_A +
        (warpM * 64 + (lane & 15)) * APITCH + ((lane >> 4) * 8) * 2;

    for (int nc = 0; nc < 3; nc++) {
        float c[4][4][4];
        #pragma unroll
        for (int mt = 0; mt < 4; mt++)
            #pragma unroll
            for (int nt = 0; nt < 4; nt++)
                #pragma unroll
                for (int q = 0; q < 4; q++) c[mt][nt][q] = 0.f;

        const uint2* bbase = bfrag + ((long)(nc * 16 + warpN * 4) * 48) * 32 + lane;

        #pragma unroll 2
        for (int kc = 0; kc < 12; kc++) {
            // B fragments straight from global (L2-resident)
            uint32_t bfr[4][4][2];       // [ks][nt][2]
            #pragma unroll
            for (int nt = 0; nt < 4; nt++)
                #pragma unroll
                for (int ks = 0; ks < 4; ks++) {
                    uint2 v = bbase[((long)nt * 48 + kc * 4 + ks) * 32];
                    bfr[ks][nt][0] = v.x;
                    bfr[ks][nt][1] = v.y;
                }
            #pragma unroll
            for (int ks = 0; ks < 4; ks++) {
                uint32_t afr[4][4];
                #pragma unroll
                for (int mt = 0; mt < 4; mt++) {
                    uint32_t addr = a_lane_base + mt * 16 * APITCH +
                                    (kc * 64 + ks * 16) * 2;
                    ldsm_x4(afr[mt][0], afr[mt][1], afr[mt][2], afr[mt][3], addr);
                }
                #pragma unroll
                for (int mt = 0; mt < 4; mt++)
                    #pragma unroll
                    for (int nt = 0; nt < 4; nt++)
                        mma_bf16(c[mt][nt], afr[mt], bfr[ks][nt]);
            }
        }

        // ---------- epilogue: relu(+b2) * w3, reduce into scal ----------
        const int qr = lane >> 2;
        const int qc = lane & 3;
        #pragma unroll
        for (int mt = 0; mt < 4; mt++) {
            float p0 = 0.f, p1 = 0.f;
            #pragma unroll
            for (int nt = 0; nt < 4; nt++) {
                int n0 = nc * 128 + warpN * 32 + nt * 8 + qc * 2;
                float bw0 = b2s[n0], bw1 = b2s[n0 + 1];
                float ww0 = w3s[n0], ww1 = w3s[n0 + 1];
                p0 += fmaxf(c[mt][nt][0] + bw0, 0.f) * ww0
                    + fmaxf(c[mt][nt][1] + bw1, 0.f) * ww1;
                p1 += fmaxf(c[mt][nt][2] + bw0, 0.f) * ww0
                    + fmaxf(c[mt][nt][3] + bw1, 0.f) * ww1;
            }
            p0 += __shfl_xor_sync(0xffffffffu, p0, 1);
            p0 += __shfl_xor_sync(0xffffffffu, p0, 2);
            p1 += __shfl_xor_sync(0xffffffffu, p1, 1);
            p1 += __shfl_xor_sync(0xffffffffu, p1, 2);
            if (qc == 0) {
                atomicAdd(&scal[warpM * 64 + mt * 16 + qr], p0);
                atomicAdd(&scal[warpM * 64 + mt * 16 + qr + 8], p1);
            }
        }
    }
    __syncthreads();

    // ---- sigmoid -> adj mix -> +eye ----
    if (tid < 128) {
        float x  = scal[tid] + b3p[0];
        float ew = 1.f / (1.f + expf(-x));
        scal[tid] = adj[(long)bi * 128 + tid] * ew + (tid == i ? 1.f : 0.f);
    }
    __syncthreads();
    if (tid < 32) {
        float m = fmaxf(fmaxf(scal[tid], scal[tid + 32]),
                        fmaxf(scal[tid + 64], scal[tid + 96]));
        for (int sh = 16; sh; sh >>= 1) m = fmaxf(m, __shfl_xor_sync(0xffffffffu, m, sh));
        if (tid == 0) red[0] = m;
    }
    __syncthreads();
    if (tid < 128) scal[tid] = expf(scal[tid] - red[0]);
    __syncthreads();
    if (tid < 32) {
        float s = scal[tid] + scal[tid + 32] + scal[tid + 64] + scal[tid + 96];
        for (int sh = 16; sh; sh >>= 1) s += __shfl_xor_sync(0xffffffffu, s, sh);
        if (tid == 0) red[1] = s;
    }
    __syncthreads();
    if (tid < 128) {
        float p = scal[tid] / red[1];
        a_out[(long)bi * 128 + tid] = p;
        scal[tid] = p;
    }
    __syncthreads();
    if (tid < 32) {
        float s = scal[tid] + scal[tid + 32] + scal[tid + 64] + scal[tid + 96];
        for (int sh = 16; sh; sh >>= 1) s += __shfl_xor_sync(0xffffffffu, s, sh);
        if (tid == 0) denom_out[bi] = 1.f + s;
    }
}

// ---------------- fused bias + denom + relu + LayerNorm ----------------------
__global__ __launch_bounds__(256)
void ln_kernel(const float* __restrict__ y, const float* __restrict__ gb,
               const float* __restrict__ lng, const float* __restrict__ lnb,
               const float* __restrict__ denom, float* __restrict__ outp)
{
    const int row = blockIdx.x;
    const int tid = threadIdx.x;
    const float inv = 1.f / denom[row];
    const float* yr = y + (long)row * DDIM;

    float v[3];
    float s = 0.f, sq = 0.f;
    #pragma unroll
    for (int p = 0; p < 3; p++) {
        int n = tid + p * 256;
        float x = fmaxf((yr[n] + 2.f * gb[n]) * inv, 0.f);
        v[p] = x; s += x; sq += x * x;
    }
    __shared__ float rs[8], rq[8], mm[2];
    for (int sh = 16; sh; sh >>= 1) {
        s  += __shfl_xor_sync(0xffffffffu, s,  sh);
        sq += __shfl_xor_sync(0xffffffffu, sq, sh);
    }
    if ((tid & 31) == 0) { rs[tid >> 5] = s; rq[tid >> 5] = sq; }
    __syncthreads();
    if (tid == 0) {
        float S = 0.f, Q = 0.f;
        #pragma unroll
        for (int q = 0; q < 8; q++) { S += rs[q]; Q += rq[q]; }
        float mean = S / (float)DDIM;
        float var  = Q / (float)DDIM - mean * mean;
        mm[0] = mean;
        mm[1] = rsqrtf(var + 1e-5f);
    }
    __syncthreads();
    const float mean = mm[0], rstd = mm[1];
    float* orow = outp + (long)row * DDIM;
    #pragma unroll
    for (int p = 0; p < 3; p++) {
        int n = tid + p * 256;
        orow[n] = (v[p] - mean) * rstd * lng[n] + lnb[n];
    }
}

// ---------------- zero mask tail ---------------------------------------------
__global__ void zero_tail_kernel(float* __restrict__ dst, int start, int total)
{
    int idx = start + blockIdx.x * 256 + threadIdx.x;
    if (idx < total) dst[idx] = 0.f;
}

// ---------------- launch ------------------------------------------------------
extern "C" void kernel_launch(void* const* d_in, const int* in_sizes, int n_in,
                              void* d_out, int out_size)
{
    const float* adj    = (const float*)d_in[0];
    const float* inputs = (const float*)d_in[1];
    const float* w1     = (const float*)d_in[2];
    const float* b1     = (const float*)d_in[3];
    const float* w2     = (const float*)d_in[4];
    const float* b2     = (const float*)d_in[5];
    const float* w3     = (const float*)d_in[6];
    const float* b3     = (const float*)d_in[7];
    const float* gw     = (const float*)d_in[8];
    const float* gb     = (const float*)d_in[9];
    const float* lng    = (const float*)d_in[10];
    const float* lnb    = (const float*)d_in[11];

    float *hh, *a, *denom, *t, *y, *buf;
    __nv_bfloat16* hj2;
    uint2* bfrag;
    cudaGetSymbolAddress((void**)&hh,    g_hh);
    cudaGetSymbolAddress((void**)&a,     g_a);
    cudaGetSymbolAddress((void**)&denom, g_denom);
    cudaGetSymbolAddress((void**)&t,     g_t);
    cudaGetSymbolAddress((void**)&y,     g_y);
    cudaGetSymbolAddress((void**)&buf,   g_buf);
    cudaGetSymbolAddress((void**)&hj2,   g_hj2);
    cudaGetSymbolAddress((void**)&bfrag, g_bfrag);

    static bool attr_done = false;
    if (!attr_done) {
        cudaFuncSetAttribute(edge_mma_kernel,
                             cudaFuncAttributeMaxDynamicSharedMemorySize, SM_TOTAL);
        attr_done = true;
    }

    dim3 blk(256);

    // w2 -> B fragments
    prep_bfrag<<<(48 * 48 * 32 + 255) / 256, blk>>>(w2, bfrag);

    // hi = X @ w1[:768], hj = X @ w1[768:]
    gemm_nn64<<<dim3(12, 16, 2), blk>>>(inputs, w1, hh, nullptr,
                                        ROWS, DDIM, DDIM,
                                        0L, (long)DDIM * DDIM, (long)ROWS * DDIM);
    // hj -> bf16
    prep_hj2<<<(ROWS * DDIM / 4 + 255) / 256, blk>>>(
        (const float4*)(hh + (long)ROWS * DDIM), (uint2*)hj2);

    // fused edge MLP (tensor cores) + softmax -> a, denom
    edge_mma_kernel<<<1024, blk, SM_TOTAL>>>(hh, hj2, adj, b1, bfrag, b2, w3, b3,
                                             a, denom);

    const float* cur = inputs;
    for (int li = 0; li < 3; li++) {
        gemm_nn64<<<dim3(12, 2, NBATCH), blk>>>(a, cur, t, cur,
                                                LSEQ, DDIM, LSEQ,
                                                (long)LSEQ * LSEQ,
                                                (long)LSEQ * DDIM,
                                                (long)LSEQ * DDIM);
        gemm_nn64<<<dim3(12, 16, 1), blk>>>(t, gw + (long)li * DDIM * DDIM, y, nullptr,
                                            ROWS, DDIM, DDIM, 0L, 0L, 0L);
        float* nxt = (li == 2) ? (float*)d_out
                               : buf + (long)(li & 1) * ROWS * DDIM;
        ln_kernel<<<1024, blk>>>(y, gb + li * DDIM, lng + li * DDIM, lnb + li * DDIM,
                                 denom, nxt);
        cur = nxt;
    }

    int tail = out_size - ROWS * DDIM;
    if (tail > 0)
        zero_tail_kernel<<<(tail + 255) / 256, blk>>>((float*)d_out, ROWS * DDIM, out_size);
}

// round 6
// speedup vs baseline: 1.4378x; 1.4378x over previous
#include <cuda_runtime.h>
#include <cuda_bf16.h>
#include <cstdint>

#define LSEQ 128
#define DDIM 768
#define NBATCH 8
#define ROWS (NBATCH * LSEQ)   // 1024

// ---------------- scratch (__device__ globals; no allocation) ----------------
__device__ float g_hh[2][ROWS * DDIM];   // hi, hj (fp32)
__device__ float g_a[NBATCH * LSEQ * LSEQ];
__device__ float g_denom[ROWS];
__device__ float g_t[ROWS * DDIM];
__device__ float g_y[ROWS * DDIM];
__device__ float g_buf[2][ROWS * DDIM];
__device__ __align__(16) __nv_bfloat16 g_w2t[384 * DDIM];   // w2^T bf16: [n][k]
__device__ __align__(16) __nv_bfloat16 g_hj2[ROWS * DDIM];  // hj bf16

// ============================================================================
// PTX helpers (baseline features only: sm_80-class)
// ============================================================================
__device__ __forceinline__ uint32_t smem_to_u32(const void* p) {
    uint32_t a;
    asm("{ .reg .u64 t; cvta.to.shared.u64 t, %1; cvt.u32.u64 %0, t; }" : "=r"(a) : "l"(p));
    return a;
}
#define CP_ASYNC16(dst, src) \
    asm volatile("cp.async.cg.shared.global [%0], [%1], 16;" :: "r"(dst), "l"(src))
#define CP_COMMIT() asm volatile("cp.async.commit_group;" ::: "memory")
#define CP_WAIT0()  asm volatile("cp.async.wait_group 0;" ::: "memory")

__device__ __forceinline__ void ldsm_x4(uint32_t& r0, uint32_t& r1, uint32_t& r2,
                                        uint32_t& r3, uint32_t addr) {
    asm volatile("ldmatrix.sync.aligned.m8n8.x4.shared.b16 {%0,%1,%2,%3}, [%4];"
                 : "=r"(r0), "=r"(r1), "=r"(r2), "=r"(r3) : "r"(addr));
}
__device__ __forceinline__ void ldsm_x2(uint32_t& r0, uint32_t& r1, uint32_t addr) {
    asm volatile("ldmatrix.sync.aligned.m8n8.x2.shared.b16 {%0,%1}, [%2];"
                 : "=r"(r0), "=r"(r1) : "r"(addr));
}
__device__ __forceinline__ void mma_bf16(float* c, const uint32_t* a, const uint32_t* b) {
    asm volatile("mma.sync.aligned.m16n8k16.row.col.f32.bf16.bf16.f32 "
                 "{%0,%1,%2,%3}, {%4,%5,%6,%7}, {%8,%9}, {%0,%1,%2,%3};"
                 : "+f"(c[0]), "+f"(c[1]), "+f"(c[2]), "+f"(c[3])
                 : "r"(a[0]), "r"(a[1]), "r"(a[2]), "r"(a[3]), "r"(b[0]), "r"(b[1]));
}
__device__ __forceinline__ void mma_tf32(float* c, const uint32_t* a, const uint32_t* b) {
    asm volatile("mma.sync.aligned.m16n8k8.row.col.f32.tf32.tf32.f32 "
                 "{%0,%1,%2,%3}, {%4,%5,%6,%7}, {%8,%9}, {%0,%1,%2,%3};"
                 : "+f"(c[0]), "+f"(c[1]), "+f"(c[2]), "+f"(c[3])
                 : "r"(a[0]), "r"(a[1]), "r"(a[2]), "r"(a[3]), "r"(b[0]), "r"(b[1]));
}
__device__ __forceinline__ uint32_t f2tf32(float x) {
    uint32_t r;
    asm("cvt.rna.tf32.f32 %0, %1;" : "=r"(r) : "f"(x));
    return r;
}

// ============================================================================
// tf32 tensor GEMM: C = A@B (+Cadd), row-major. BM=128, BN=64, BK=16.
// 256 threads, 8 warps as 4(M) x 2(N); warp tile 32x32 (mt=2 of m16, nt=4 of n8).
// cp.async double-buffered. M%128==0, N%64==0, K%16==0.
// ============================================================================
#define TAP 20    // As pitch (floats): 16 + 4 pad
#define TBP 72    // Bs pitch (floats): 64 + 8 pad

__global__ __launch_bounds__(256)
void gemm_tf32(const float* __restrict__ A, const float* __restrict__ B,
               float* __restrict__ C, const float* __restrict__ Cadd,
               int M, int N, int K, long sA, long sB, long sC)
{
    const int bz = blockIdx.z;
    A += (long)bz * sA;
    B += (long)bz * sB;
    const long coff = (long)bz * sC;

    const int bm = blockIdx.y * 128;
    const int bn = blockIdx.x * 64;

    __shared__ float As[2][128][TAP];
    __shared__ float Bs[2][16][TBP];

    const int tid  = threadIdx.x;
    const int lane = tid & 31;
    const int wid  = tid >> 5;
    const int warpM = wid >> 1;          // 0..3 (32 rows each)
    const int warpN = wid & 1;           // 0..1 (32 cols each)
    const int gr = lane >> 2;            // 0..7
    const int gc = lane & 3;             // 0..3

    const uint32_t sbase = smem_to_u32(&As[0][0][0]);
    const uint32_t bbase = smem_to_u32(&Bs[0][0][0]);

    // cp.async source/dest precompute
    const int arow = tid >> 1;           // 0..127
    const int akq  = (tid & 1) * 8;      // 0 or 8
    const int bk   = tid >> 4;           // 0..15
    const int bn4  = (tid & 15) * 4;     // 0..60

    const int nK = K >> 4;

    // ---- stage chunk 0 ----
    {
        const float* as = A + (long)(bm + arow) * K + akq;
        uint32_t ad = sbase + (arow * TAP + akq) * 4;
        CP_ASYNC16(ad, as);
        CP_ASYNC16(ad + 16, as + 4);
        const float* bs = B + (long)bk * N + bn + bn4;
        uint32_t bd = bbase + (bk * TBP + bn4) * 4;
        CP_ASYNC16(bd, bs);
        CP_COMMIT();
    }

    float c[2][4][4];
    #pragma unroll
    for (int mt = 0; mt < 2; mt++)
        #pragma unroll
        for (int nt = 0; nt < 4; nt++)
            #pragma unroll
            for (int q = 0; q < 4; q++) c[mt][nt][q] = 0.f;

    for (int ki = 0; ki < nK; ki++) {
        CP_WAIT0();
        __syncthreads();
        const int cur = ki & 1;
        if (ki + 1 < nK) {
            const int nxt = cur ^ 1;
            const int kc = (ki + 1) * 16;
            const float* as = A + (long)(bm + arow) * K + kc + akq;
            uint32_t ad = sbase + (nxt * 128 * TAP + arow * TAP + akq) * 4;
            CP_ASYNC16(ad, as);
            CP_ASYNC16(ad + 16, as + 4);
            const float* bs = B + (long)(kc + bk) * N + bn + bn4;
            uint32_t bd = bbase + (nxt * 16 * TBP + bk * TBP + bn4) * 4;
            CP_ASYNC16(bd, bs);
            CP_COMMIT();
        }

        #pragma unroll
        for (int k8 = 0; k8 < 16; k8 += 8) {
            uint32_t a[2][4];
            #pragma unroll
            for (int mt = 0; mt < 2; mt++) {
                int r0 = warpM * 32 + mt * 16 + gr;
                a[mt][0] = f2tf32(As[cur][r0    ][k8 + gc]);
                a[mt][1] = f2tf32(As[cur][r0 + 8][k8 + gc]);
                a[mt][2] = f2tf32(As[cur][r0    ][k8 + gc + 4]);
                a[mt][3] = f2tf32(As[cur][r0 + 8][k8 + gc + 4]);
            }
            uint32_t b[4][2];
            #pragma unroll
            for (int nt = 0; nt < 4; nt++) {
                int n = warpN * 32 + nt * 8 + gr;
                b[nt][0] = f2tf32(Bs[cur][k8 + gc    ][n]);
                b[nt][1] = f2tf32(Bs[cur][k8 + gc + 4][n]);
            }
            #pragma unroll
            for (int mt = 0; mt < 2; mt++)
                #pragma unroll
                for (int nt = 0; nt < 4; nt++)
                    mma_tf32(c[mt][nt], a[mt], b[nt]);
        }
    }

    // ---- epilogue ----
    #pragma unroll
    for (int mt = 0; mt < 2; mt++) {
        #pragma unroll
        for (int nt = 0; nt < 4; nt++) {
            int row0 = bm + warpM * 32 + mt * 16 + gr;
            int col  = bn + warpN * 32 + nt * 8 + gc * 2;
            long o0 = coff + (long)row0 * N + col;
            long o1 = coff + (long)(row0 + 8) * N + col;
            float2 v0 = make_float2(c[mt][nt][0], c[mt][nt][1]);
            float2 v1 = make_float2(c[mt][nt][2], c[mt][nt][3]);
            if (Cadd) {
                float2 w0 = *(const float2*)(Cadd + o0);
                float2 w1 = *(const float2*)(Cadd + o1);
                v0.x += w0.x; v0.y += w0.y;
                v1.x += w1.x; v1.y += w1.y;
            }
            *(float2*)(C + o0) = v0;
            *(float2*)(C + o1) = v1;
        }
    }
}

// ---------------- prep: w2^T bf16, hj bf16 -----------------------------------
__global__ void prep_w2t(const float* __restrict__ w2, __nv_bfloat16* __restrict__ w2t)
{
    int idx = blockIdx.x * 256 + threadIdx.x;
    if (idx < 384 * DDIM) {
        int n = idx / DDIM, k = idx % DDIM;
        w2t[idx] = __float2bfloat16(w2[k * 384 + n]);
    }
}
__global__ void prep_hj2(const float4* __restrict__ hj, uint2* __restrict__ hj2)
{
    int idx = blockIdx.x * 256 + threadIdx.x;
    if (idx < ROWS * DDIM / 4) {
        float4 v = hj[idx];
        __nv_bfloat162 lo = __floats2bfloat162_rn(v.x, v.y);
        __nv_bfloat162 hi = __floats2bfloat162_rn(v.z, v.w);
        uint2 o; o.x = *(uint32_t*)&lo; o.y = *(uint32_t*)&hi;
        hj2[idx] = o;
    }
}

// ============================================================================
// Fused edge-MLP via mma.sync bf16 (R4 version). One CTA per (b, i).
// ============================================================================
#define APITCH 144                       // 72 bf16 per row (64 data + pad)
#define ABUF   18432                     // 128 * 144
#define SM_A     0
#define SM_B     36864
#define SM_HIB   73728
#define SM_B2    76800
#define SM_W3    78336
#define SM_SCAL  79872
#define SM_RED   80384
#define SM_TOTAL 80448

__global__ __launch_bounds__(256)
void edge_mma_kernel(const float* __restrict__ hi, const __nv_bfloat16* __restrict__ hj2,
                     const float* __restrict__ adj, const float* __restrict__ b1,
                     const __nv_bfloat16* __restrict__ w2t, const float* __restrict__ b2,
                     const float* __restrict__ w3, const float* __restrict__ b3p,
                     float* __restrict__ a_out, float* __restrict__ denom_out)
{
    extern __shared__ char smem[];
    const uint32_t sbase = smem_to_u32(smem);
    const int tid  = threadIdx.x;
    const int lane = tid & 31;
    const int wid  = tid >> 5;
    const int warpM = wid >> 2;          // 0..1
    const int warpN = wid & 3;           // 0..3
    const int bi = blockIdx.x;
    const int b  = bi >> 7;
    const int i  = bi & 127;

    float* hib  = (float*)(smem + SM_HIB);
    float* b2s  = (float*)(smem + SM_B2);
    float* w3s  = (float*)(smem + SM_W3);
    float* scal = (float*)(smem + SM_SCAL);
    float* red  = (float*)(smem + SM_RED);

    for (int k = tid; k < DDIM; k += 256) hib[k] = hi[(long)bi * DDIM + k] + b1[k];
    for (int k = tid; k < 384; k += 256) { b2s[k] = b2[k]; w3s[k] = w3[k]; }
    if (tid < 128) scal[tid] = 0.f;
    __syncthreads();

    // A-build mapping: thread -> (row j, k-half)
    const int aj = tid >> 1;
    const int ah = tid & 1;
    const __nv_bfloat16* hjrow = hj2 + ((long)b * LSEQ + aj) * DDIM + ah * 32;
    const char* abase_th = smem + SM_A + aj * APITCH + ah * 64;

    for (int nc = 0; nc < 3; nc++) {
        float c[4][4][4];
        #pragma unroll
        for (int mt = 0; mt < 4; mt++)
            #pragma unroll
            for (int nt = 0; nt < 4; nt++)
                #pragma unroll
                for (int q = 0; q < 4; q++) c[mt][nt][q] = 0.f;

        // ---------- prologue: stage chunk 0 ----------
        {
            const uint4* src = (const uint4*)(hjrow + 0);
            const float* hb  = hib + 0 + ah * 32;
            #pragma unroll
            for (int s = 0; s < 4; s++) {
                uint4 v = src[s];
                __nv_bfloat162* p = (__nv_bfloat162*)&v;
                uint4 o;
                uint32_t* po = (uint32_t*)&o;
                #pragma unroll
                for (int h = 0; h < 4; h++) {
                    float2 f = __bfloat1622float2(p[h]);
                    __nv_bfloat162 r = __floats2bfloat162_rn(
                        fmaxf(f.x + hb[s * 8 + h * 2], 0.f),
                        fmaxf(f.y + hb[s * 8 + h * 2 + 1], 0.f));
                    po[h] = *(uint32_t*)&r;
                }
                *(uint4*)(abase_th + s * 16) = o;
            }
            #pragma unroll
            for (int s = 0; s < 4; s++) {
                int idx = s * 256 + tid;
                int n = idx >> 3, q = idx & 7;
                uint32_t dst = sbase + SM_B + n * APITCH + q * 16;
                const __nv_bfloat16* srcb = w2t + ((long)(nc * 128 + n) * DDIM + q * 8);
                CP_ASYNC16(dst, srcb);
            }
            CP_COMMIT();
            CP_WAIT0();
            __syncthreads();
        }

        for (int kc = 0; kc < 12; kc++) {
            const int cur = kc & 1;
            // ---------- stage next chunk ----------
            if (kc < 11) {
                const int nxt = cur ^ 1;
                const int k0 = (kc + 1) * 64;
                const uint4* src = (const uint4*)(hjrow + k0);
                const float* hb  = hib + k0 + ah * 32;
                char* ab = (char*)abase_th + nxt * ABUF;
                #pragma unroll
                for (int s = 0; s < 4; s++) {
                    uint4 v = src[s];
                    __nv_bfloat162* p = (__nv_bfloat162*)&v;
                    uint4 o;
                    uint32_t* po = (uint32_t*)&o;
                    #pragma unroll
                    for (int h = 0; h < 4; h++) {
                        float2 f = __bfloat1622float2(p[h]);
                        __nv_bfloat162 r = __floats2bfloat162_rn(
                            fmaxf(f.x + hb[s * 8 + h * 2], 0.f),
                            fmaxf(f.y + hb[s * 8 + h * 2 + 1], 0.f));
                        po[h] = *(uint32_t*)&r;
                    }
                    *(uint4*)(ab + s * 16) = o;
                }
                #pragma unroll
                for (int s = 0; s < 4; s++) {
                    int idx = s * 256 + tid;
                    int n = idx >> 3, q = idx & 7;
                    uint32_t dst = sbase + SM_B + nxt * ABUF + n * APITCH + q * 16;
                    const __nv_bfloat16* srcb =
                        w2t + ((long)(nc * 128 + n) * DDIM + k0 + q * 8);
                    CP_ASYNC16(dst, srcb);
                }
                CP_COMMIT();
            }

            // ---------- MMA on current chunk ----------
            const uint32_t abase = sbase + SM_A + cur * ABUF;
            const uint32_t bbase = sbase + SM_B + cur * ABUF;
            #pragma unroll
            for (int ks = 0; ks < 4; ks++) {
                uint32_t afr[4][4];
                #pragma unroll
                for (int mt = 0; mt < 4; mt++) {
                    uint32_t addr = abase +
                        (warpM * 64 + mt * 16 + (lane & 15)) * APITCH +
                        (ks * 16 + (lane >> 4) * 8) * 2;
                    ldsm_x4(afr[mt][0], afr[mt][1], afr[mt][2], afr[mt][3], addr);
                }
                uint32_t bfr[4][2];
                #pragma unroll
                for (int nt = 0; nt < 4; nt++) {
                    uint32_t addr = bbase +
                        (warpN * 32 + nt * 8 + (lane & 7)) * APITCH +
                        (ks * 16 + ((lane >> 3) & 1) * 8) * 2;
                    ldsm_x2(bfr[nt][0], bfr[nt][1], addr);
                }
                #pragma unroll
                for (int mt = 0; mt < 4; mt++)
                    #pragma unroll
                    for (int nt = 0; nt < 4; nt++)
                        mma_bf16(c[mt][nt], afr[mt], bfr[nt]);
            }

            if (kc < 11) CP_WAIT0();
            __syncthreads();
        }

        // ---------- epilogue: relu(+b2) * w3, reduce into scal ----------
        const int qr = lane >> 2;
        const int qc = lane & 3;
        #pragma unroll
        for (int mt = 0; mt < 4; mt++) {
            float p0 = 0.f, p1 = 0.f;
            #pragma unroll
            for (int nt = 0; nt < 4; nt++) {
                int n0 = nc * 128 + warpN * 32 + nt * 8 + qc * 2;
                float bw0 = b2s[n0], bw1 = b2s[n0 + 1];
                float ww0 = w3s[n0], ww1 = w3s[n0 + 1];
                p0 += fmaxf(c[mt][nt][0] + bw0, 0.f) * ww0
                    + fmaxf(c[mt][nt][1] + bw1, 0.f) * ww1;
                p1 += fmaxf(c[mt][nt][2] + bw0, 0.f) * ww0
                    + fmaxf(c[mt][nt][3] + bw1, 0.f) * ww1;
            }
            p0 += __shfl_xor_sync(0xffffffffu, p0, 1);
            p0 += __shfl_xor_sync(0xffffffffu, p0, 2);
            p1 += __shfl_xor_sync(0xffffffffu, p1, 1);
            p1 += __shfl_xor_sync(0xffffffffu, p1, 2);
            if (qc == 0) {
                atomicAdd(&scal[warpM * 64 + mt * 16 + qr], p0);
                atomicAdd(&scal[warpM * 64 + mt * 16 + qr + 8], p1);
            }
        }
        __syncthreads();
    }

    // ---- sigmoid -> adj mix -> +eye ----
    if (tid < 128) {
        float x  = scal[tid] + b3p[0];
        float ew = 1.f / (1.f + expf(-x));
        scal[tid] = adj[(long)bi * 128 + tid] * ew + (tid == i ? 1.f : 0.f);
    }
    __syncthreads();
    if (tid < 32) {
        float m = fmaxf(fmaxf(scal[tid], scal[tid + 32]),
                        fmaxf(scal[tid + 64], scal[tid + 96]));
        for (int sh = 16; sh; sh >>= 1) m = fmaxf(m, __shfl_xor_sync(0xffffffffu, m, sh));
        if (tid == 0) red[0] = m;
    }
    __syncthreads();
    if (tid < 128) scal[tid] = expf(scal[tid] - red[0]);
    __syncthreads();
    if (tid < 32) {
        float s = scal[tid] + scal[tid + 32] + scal[tid + 64] + scal[tid + 96];
        for (int sh = 16; sh; sh >>= 1) s += __shfl_xor_sync(0xffffffffu, s, sh);
        if (tid == 0) red[1] = s;
    }
    __syncthreads();
    if (tid < 128) {
        float p = scal[tid] / red[1];
        a_out[(long)bi * 128 + tid] = p;
        scal[tid] = p;
    }
    __syncthreads();
    if (tid < 32) {
        float s = scal[tid] + scal[tid + 32] + scal[tid + 64] + scal[tid + 96];
        for (int sh = 16; sh; sh >>= 1) s += __shfl_xor_sync(0xffffffffu, s, sh);
        if (tid == 0) denom_out[bi] = 1.f + s;
    }
}

// ---------------- fused bias + denom + relu + LayerNorm ----------------------
__global__ __launch_bounds__(256)
void ln_kernel(const float* __restrict__ y, const float* __restrict__ gb,
               const float* __restrict__ lng, const float* __restrict__ lnb,
               const float* __restrict__ denom, float* __restrict__ outp)
{
    const int row = blockIdx.x;
    const int tid = threadIdx.x;
    const float inv = 1.f / denom[row];
    const float* yr = y + (long)row * DDIM;

    float v[3];
    float s = 0.f, sq = 0.f;
    #pragma unroll
    for (int p = 0; p < 3; p++) {
        int n = tid + p * 256;
        float x = fmaxf((yr[n] + 2.f * gb[n]) * inv, 0.f);
        v[p] = x; s += x; sq += x * x;
    }
    __shared__ float rs[8], rq[8], mm[2];
    for (int sh = 16; sh; sh >>= 1) {
        s  += __shfl_xor_sync(0xffffffffu, s,  sh);
        sq += __shfl_xor_sync(0xffffffffu, sq, sh);
    }
    if ((tid & 31) == 0) { rs[tid >> 5] = s; rq[tid >> 5] = sq; }
    __syncthreads();
    if (tid == 0) {
        float S = 0.f, Q = 0.f;
        #pragma unroll
        for (int q = 0; q < 8; q++) { S += rs[q]; Q += rq[q]; }
        float mean = S / (float)DDIM;
        float var  = Q / (float)DDIM - mean * mean;
        mm[0] = mean;
        mm[1] = rsqrtf(var + 1e-5f);
    }
    __syncthreads();
    const float mean = mm[0], rstd = mm[1];
    float* orow = outp + (long)row * DDIM;
    #pragma unroll
    for (int p = 0; p < 3; p++) {
        int n = tid + p * 256;
        orow[n] = (v[p] - mean) * rstd * lng[n] + lnb[n];
    }
}

// ---------------- zero mask tail ---------------------------------------------
__global__ void zero_tail_kernel(float* __restrict__ dst, int start, int total)
{
    int idx = start + blockIdx.x * 256 + threadIdx.x;
    if (idx < total) dst[idx] = 0.f;
}

// ---------------- launch ------------------------------------------------------
extern "C" void kernel_launch(void* const* d_in, const int* in_sizes, int n_in,
                              void* d_out, int out_size)
{
    const float* adj    = (const float*)d_in[0];
    const float* inputs = (const float*)d_in[1];
    const float* w1     = (const float*)d_in[2];
    const float* b1     = (const float*)d_in[3];
    const float* w2     = (const float*)d_in[4];
    const float* b2     = (const float*)d_in[5];
    const float* w3     = (const float*)d_in[6];
    const float* b3     = (const float*)d_in[7];
    const float* gw     = (const float*)d_in[8];
    const float* gb     = (const float*)d_in[9];
    const float* lng    = (const float*)d_in[10];
    const float* lnb    = (const float*)d_in[11];

    float *hh, *a, *denom, *t, *y, *buf;
    __nv_bfloat16 *w2t, *hj2;
    cudaGetSymbolAddress((void**)&hh,    g_hh);
    cudaGetSymbolAddress((void**)&a,     g_a);
    cudaGetSymbolAddress((void**)&denom, g_denom);
    cudaGetSymbolAddress((void**)&t,     g_t);
    cudaGetSymbolAddress((void**)&y,     g_y);
    cudaGetSymbolAddress((void**)&buf,   g_buf);
    cudaGetSymbolAddress((void**)&w2t,   g_w2t);
    cudaGetSymbolAddress((void**)&hj2,   g_hj2);

    static bool attr_done = false;
    if (!attr_done) {
        cudaFuncSetAttribute(edge_mma_kernel,
                             cudaFuncAttributeMaxDynamicSharedMemorySize, SM_TOTAL);
        attr_done = true;
    }

    dim3 blk(256);

    // w2 -> bf16 transposed
    prep_w2t<<<(384 * DDIM + 255) / 256, blk>>>(w2, w2t);

    // hi = X @ w1[:768], hj = X @ w1[768:]   (tf32 tensor GEMM)
    gemm_tf32<<<dim3(12, 8, 2), blk>>>(inputs, w1, hh, nullptr,
                                       ROWS, DDIM, DDIM,
                                       0L, (long)DDIM * DDIM, (long)ROWS * DDIM);
    // hj -> bf16
    prep_hj2<<<(ROWS * DDIM / 4 + 255) / 256, blk>>>(
        (const float4*)(hh + (long)ROWS * DDIM), (uint2*)hj2);

    // fused edge MLP (tensor cores via mma.sync) + softmax -> a, denom
    edge_mma_kernel<<<1024, blk, SM_TOTAL>>>(hh, hj2, adj, b1, w2t, b2, w3, b3,
                                             a, denom);

    const float* cur = inputs;
    for (int li = 0; li < 3; li++) {
        // t = a @ cur + cur   (per batch, tf32)
        gemm_tf32<<<dim3(12, 1, NBATCH), blk>>>(a, cur, t, cur,
                                                LSEQ, DDIM, LSEQ,
                                                (long)LSEQ * LSEQ,
                                                (long)LSEQ * DDIM,
                                                (long)LSEQ * DDIM);
        // y = t @ gw[li]   (tf32)
        gemm_tf32<<<dim3(12, 8, 1), blk>>>(t, gw + (long)li * DDIM * DDIM, y, nullptr,
                                           ROWS, DDIM, DDIM, 0L, 0L, 0L);
        float* nxt = (li == 2) ? (float*)d_out
                               : buf + (long)(li & 1) * ROWS * DDIM;
        ln_kernel<<<1024, blk>>>(y, gb + li * DDIM, lng + li * DDIM, lnb + li * DDIM,
                                 denom, nxt);
        cur = nxt;
    }

    int tail = out_size - ROWS * DDIM;
    if (tail > 0)
        zero_tail_kernel<<<(tail + 255) / 256, blk>>>((float*)d_out, ROWS * DDIM, out_size);
}